// round 2
// baseline (speedup 1.0000x reference)
#include <cuda_runtime.h>
#include <cuda_bf16.h>
#include <cuda_fp16.h>
#include <cstdint>

#define HF 128
#define NNODES 100000
#define NODES_PAD 100096
#define MTILES 782   // ceil(100000/128)
#define AST 136      // padded row stride in halves (272B)

// ---------------- device scratch (no runtime allocation allowed) ----------------
__device__ __half g_P[(size_t)3 * NODES_PAD * HF];           // 76.9 MB fp16 P tables
__device__ __nv_bfloat16 g_Bp[3][2][128 * AST];              // B images hi/lo, padded
__device__ int g_is64;

// ---------------- mma.sync helpers (compute_100-safe) ----------------
static __device__ __forceinline__ void ldsm4(uint32_t* r, const void* p) {
    uint32_t a = (uint32_t)__cvta_generic_to_shared(p);
    asm volatile("ldmatrix.sync.aligned.m8n8.x4.shared.b16 {%0,%1,%2,%3}, [%4];"
                 : "=r"(r[0]), "=r"(r[1]), "=r"(r[2]), "=r"(r[3]) : "r"(a));
}
static __device__ __forceinline__ void mma16816(float* c, const uint32_t* a,
                                                uint32_t b0, uint32_t b1) {
    asm volatile(
        "mma.sync.aligned.m16n8k16.row.col.f32.bf16.bf16.f32 "
        "{%0,%1,%2,%3}, {%4,%5,%6,%7}, {%8,%9}, {%0,%1,%2,%3};"
        : "+f"(c[0]), "+f"(c[1]), "+f"(c[2]), "+f"(c[3])
        : "r"(a[0]), "r"(a[1]), "r"(a[2]), "r"(a[3]), "r"(b0), "r"(b1));
}
static __device__ __forceinline__ void split_bf16(float v, unsigned short& hi, unsigned short& lo) {
    __nv_bfloat16 h = __float2bfloat16_rn(v);
    float r = v - __bfloat162float(h);
    __nv_bfloat16 l = __float2bfloat16_rn(r);
    hi = __bfloat16_as_ushort(h);
    lo = __bfloat16_as_ushort(l);
}

// ---------------- kernel 0: detect triplet dtype (int32 vs int64) ----------------
__global__ void detect_kernel(const unsigned* __restrict__ w, int total_words) {
    __shared__ int zc, ts;
    if (threadIdx.x == 0) { zc = 0; ts = 0; }
    __syncthreads();
    int maxi = (total_words - 1) >> 1;
    int samples = maxi < 4096 ? maxi : 4096;
    int stride = samples > 0 ? (maxi / samples) : 1;
    if (stride < 1) stride = 1;
    int lz = 0, lt = 0;
    for (int s = threadIdx.x; s < samples; s += blockDim.x) {
        int i = s * stride;
        lt++;
        if (w[2 * i + 1] == 0u) lz++;
    }
    atomicAdd(&zc, lz);
    atomicAdd(&ts, lt);
    __syncthreads();
    if (threadIdx.x == 0) g_is64 = (2 * zc > ts) ? 1 : 0;
}

// ---------------- kernel 1: build padded B images (bf16 hi/lo) from W1 ----------------
// B[j][n][k] = W1_w[n][j*128 + k]
__global__ void prep_B(const float* __restrict__ W1) {
    int idx = blockIdx.x * blockDim.x + threadIdx.x;
    if (idx >= 3 * 128 * 64) return;
    int j = idx / 8192;
    int rem = idx - j * 8192;
    int row = rem >> 6;        // n (hid index)
    int kp = rem & 63;         // k pair
    int k = kp << 1;
    float v0 = W1[row * 384 + j * 128 + k];
    float v1 = W1[row * 384 + j * 128 + k + 1];
    unsigned short h0, l0, h1, l1;
    split_bf16(v0, h0, l0);
    split_bf16(v1, h1, l1);
    uint32_t off = (uint32_t)row * AST + (uint32_t)k;   // halves
    *(uint32_t*)&g_Bp[j][0][off] = (uint32_t)h0 | ((uint32_t)h1 << 16);
    *(uint32_t*)&g_Bp[j][1][off] = (uint32_t)l0 | ((uint32_t)l1 << 16);
}

// ---------------- kernel 2: P = h @ W1^T via 3-pass split-bf16 mma.sync ----------------
#define SMEM_HALVES (128 * AST)
#define SMEM_TOTAL (4 * SMEM_HALVES * 2)   // 139264 bytes

__global__ void __launch_bounds__(256, 1) gemm_P(const float* __restrict__ hmat) {
    extern __shared__ __nv_bfloat16 sm[];
    __nv_bfloat16* Ah = sm;
    __nv_bfloat16* Al = sm + SMEM_HALVES;
    __nv_bfloat16* Bh = sm + 2 * SMEM_HALVES;
    __nv_bfloat16* Bl = sm + 3 * SMEM_HALVES;

    int tid = threadIdx.x, w = tid >> 5, lane = tid & 31;
    int base = blockIdx.x * 128;

    // Load + split A tile [128 rows x 128 K] into padded smem
    for (int p = tid; p < 128 * 64; p += 256) {
        int row = p >> 6, kp = p & 63;
        int node = base + row;
        float2 t = make_float2(0.f, 0.f);
        if (node < NNODES) t = *(const float2*)(hmat + (size_t)node * HF + (kp << 1));
        unsigned short h0, l0, h1, l1;
        split_bf16(t.x, h0, l0);
        split_bf16(t.y, h1, l1);
        uint32_t off = (uint32_t)row * AST + (uint32_t)(kp << 1);
        *(uint32_t*)&Ah[off] = (uint32_t)h0 | ((uint32_t)h1 << 16);
        *(uint32_t*)&Al[off] = (uint32_t)l0 | ((uint32_t)l1 << 16);
    }

    // per-lane ldmatrix row mapping
    int mrow = w * 16;
    int a_row = lane & 15;
    int a_koff = (lane >> 4) << 3;
    int b_nrow = (lane & 7) + ((lane >> 4) << 3);
    int b_koff = ((lane >> 3) & 1) << 3;

    for (int j = 0; j < 3; j++) {
        __syncthreads();
        // stage B_j hi/lo into smem (straight copy, 16B aligned: 272B rows)
        {
            const uint4* sh = (const uint4*)g_Bp[j][0];
            const uint4* sl = (const uint4*)g_Bp[j][1];
            uint4* dh = (uint4*)Bh;
            uint4* dl = (uint4*)Bl;
            const int NV = SMEM_HALVES * 2 / 16;  // 2176
            for (int i = tid; i < NV; i += 256) { dh[i] = sh[i]; dl[i] = sl[i]; }
        }
        __syncthreads();

        float acc[16][4];
        #pragma unroll
        for (int t = 0; t < 16; t++)
            #pragma unroll
            for (int q = 0; q < 4; q++) acc[t][q] = 0.f;

        #pragma unroll
        for (int ks = 0; ks < 8; ks++) {
            int kb = ks * 16;
            uint32_t ah[4], al[4];
            ldsm4(ah, &Ah[(mrow + a_row) * AST + kb + a_koff]);
            ldsm4(al, &Al[(mrow + a_row) * AST + kb + a_koff]);
            #pragma unroll
            for (int np = 0; np < 8; np++) {
                uint32_t bh[4], bl[4];
                ldsm4(bh, &Bh[(np * 16 + b_nrow) * AST + kb + b_koff]);
                ldsm4(bl, &Bl[(np * 16 + b_nrow) * AST + kb + b_koff]);
                // tile nt = 2*np  (cols np*16 .. +7)
                mma16816(acc[2 * np], ah, bh[0], bh[1]);        // hi*hi
                mma16816(acc[2 * np], ah, bl[0], bl[1]);        // hi*lo
                mma16816(acc[2 * np], al, bh[0], bh[1]);        // lo*hi
                // tile nt = 2*np+1 (cols np*16+8 .. +15)
                mma16816(acc[2 * np + 1], ah, bh[2], bh[3]);
                mma16816(acc[2 * np + 1], ah, bl[2], bl[3]);
                mma16816(acc[2 * np + 1], al, bh[2], bh[3]);
            }
        }

        // Write results: thread holds rows (groupID, groupID+8), col pairs
        int r0 = base + mrow + (lane >> 2);
        int c0 = (lane & 3) * 2;
        __half* Pj = g_P + (size_t)j * NODES_PAD * HF;
        #pragma unroll
        for (int nt = 0; nt < 16; nt++) {
            int col = nt * 8 + c0;
            if (r0 < NNODES) {
                __half2 v = __floats2half2_rn(acc[nt][0], acc[nt][1]);
                *(__half2*)(Pj + (size_t)r0 * HF + col) = v;
            }
            if (r0 + 8 < NNODES) {
                __half2 v = __floats2half2_rn(acc[nt][2], acc[nt][3]);
                *(__half2*)(Pj + (size_t)(r0 + 8) * HF + col) = v;
            }
        }
    }
}

// ---------------- kernel 3: gather + add + relu + layer-2 ----------------
__global__ void __launch_bounds__(256) mlp2_kernel(const void* __restrict__ trip,
                                                   const float* __restrict__ Wb1,
                                                   const float* __restrict__ W2,
                                                   const float* __restrict__ Wb2,
                                                   float* __restrict__ out, int T) {
    int gw = (int)((blockIdx.x * blockDim.x + threadIdx.x) >> 5);
    int lid = threadIdx.x & 31;
    if (gw >= T) return;

    long long t0, t1, t2;
    if (g_is64) {
        const long long* tp = (const long long*)trip + 3ll * gw;
        t0 = tp[0]; t1 = tp[1]; t2 = tp[2];
    } else {
        const int* tp = (const int*)trip + 3 * gw;
        t0 = tp[0]; t1 = tp[1]; t2 = tp[2];
    }

    int col = lid << 2;  // 4 hid columns per lane
    uint2 ua = *(const uint2*)(g_P + (size_t)t0 * HF + col);
    uint2 ub = *(const uint2*)(g_P + ((size_t)NODES_PAD + (size_t)t1) * HF + col);
    uint2 uc = *(const uint2*)(g_P + ((size_t)2 * NODES_PAD + (size_t)t2) * HF + col);

    float2 fa0 = __half22float2(*reinterpret_cast<const __half2*>(&ua.x));
    float2 fa1 = __half22float2(*reinterpret_cast<const __half2*>(&ua.y));
    float2 fb0 = __half22float2(*reinterpret_cast<const __half2*>(&ub.x));
    float2 fb1 = __half22float2(*reinterpret_cast<const __half2*>(&ub.y));
    float2 fc0 = __half22float2(*reinterpret_cast<const __half2*>(&uc.x));
    float2 fc1 = __half22float2(*reinterpret_cast<const __half2*>(&uc.y));

    const float4 bias = *(const float4*)(Wb1 + col);
    float h0 = fmaxf(fa0.x + fb0.x + fc0.x + bias.x, 0.f);
    float h1 = fmaxf(fa0.y + fb0.y + fc0.y + bias.y, 0.f);
    float h2 = fmaxf(fa1.x + fb1.x + fc1.x + bias.z, 0.f);
    float h3 = fmaxf(fa1.y + fb1.y + fc1.y + bias.w, 0.f);

    const float4 w0 = *(const float4*)(W2 + col);
    const float4 w1 = *(const float4*)(W2 + HF + col);
    float acc0 = h0 * w0.x + h1 * w0.y + h2 * w0.z + h3 * w0.w;
    float acc1 = h0 * w1.x + h1 * w1.y + h2 * w1.z + h3 * w1.w;

    #pragma unroll
    for (int m = 16; m; m >>= 1) {
        acc0 += __shfl_xor_sync(0xffffffffu, acc0, m);
        acc1 += __shfl_xor_sync(0xffffffffu, acc1, m);
    }
    if (lid == 0) {
        float2 o;
        o.x = acc0 + Wb2[0];
        o.y = acc1 + Wb2[1];
        *(float2*)(out + 2ll * gw) = o;
    }
}

// ---------------- launch ----------------
extern "C" void kernel_launch(void* const* d_in, const int* in_sizes, int n_in,
                              void* d_out, int out_size) {
    const float* hmat = (const float*)d_in[0];
    const void* trip = d_in[1];
    const float* W1w = (const float*)d_in[2];
    const float* W1b = (const float*)d_in[3];
    const float* W2w = (const float*)d_in[4];
    const float* W2b = (const float*)d_in[5];
    float* out = (float*)d_out;
    int T = in_sizes[1] / 3;

    static int smem_set = 0;
    if (!smem_set) {
        cudaFuncSetAttribute(gemm_P, cudaFuncAttributeMaxDynamicSharedMemorySize, SMEM_TOTAL);
        smem_set = 1;
    }

    detect_kernel<<<1, 256>>>((const unsigned*)trip, in_sizes[1]);
    prep_B<<<(3 * 128 * 64 + 255) / 256, 256>>>(W1w);
    gemm_P<<<MTILES, 256, SMEM_TOTAL>>>(hmat);
    mlp2_kernel<<<(T + 7) / 8, 256>>>(trip, W1b, W2w, W2b, out, T);
}

// round 3
// speedup vs baseline: 1.6210x; 1.6210x over previous
#include <cuda_runtime.h>
#include <cuda_bf16.h>
#include <cuda_fp16.h>
#include <cstdint>

#define HF 128
#define NNODES 100000
#define NODES_PAD 100096
#define MTILES 782   // ceil(100000/128)
#define AST 136      // padded row stride in halves (272B)

// ---------------- device scratch ----------------
__device__ __half g_P[(size_t)3 * NODES_PAD * HF];   // 76.9 MB fp16 P tables
__device__ __half g_Bf[3][128 * AST];                // fp16 padded B images
__device__ int g_is64;

// ---------------- mma.sync helpers (compute_100-safe) ----------------
static __device__ __forceinline__ void ldsm4(uint32_t* r, const void* p) {
    uint32_t a = (uint32_t)__cvta_generic_to_shared(p);
    asm volatile("ldmatrix.sync.aligned.m8n8.x4.shared.b16 {%0,%1,%2,%3}, [%4];"
                 : "=r"(r[0]), "=r"(r[1]), "=r"(r[2]), "=r"(r[3]) : "r"(a));
}
static __device__ __forceinline__ void mma_f16(float* c, const uint32_t* a,
                                               uint32_t b0, uint32_t b1) {
    asm volatile(
        "mma.sync.aligned.m16n8k16.row.col.f32.f16.f16.f32 "
        "{%0,%1,%2,%3}, {%4,%5,%6,%7}, {%8,%9}, {%0,%1,%2,%3};"
        : "+f"(c[0]), "+f"(c[1]), "+f"(c[2]), "+f"(c[3])
        : "r"(a[0]), "r"(a[1]), "r"(a[2]), "r"(a[3]), "r"(b0), "r"(b1));
}

// ---------------- kernel 0: detect triplet dtype ----------------
__global__ void detect_kernel(const unsigned* __restrict__ w, int total_words) {
    __shared__ int zc, ts;
    if (threadIdx.x == 0) { zc = 0; ts = 0; }
    __syncthreads();
    int maxi = (total_words - 1) >> 1;
    int samples = maxi < 4096 ? maxi : 4096;
    int stride = samples > 0 ? (maxi / samples) : 1;
    if (stride < 1) stride = 1;
    int lz = 0, lt = 0;
    for (int s = threadIdx.x; s < samples; s += blockDim.x) {
        int i = s * stride;
        lt++;
        if (w[2 * i + 1] == 0u) lz++;
    }
    atomicAdd(&zc, lz);
    atomicAdd(&ts, lt);
    __syncthreads();
    if (threadIdx.x == 0) g_is64 = (2 * zc > ts) ? 1 : 0;
}

// ---------------- kernel 1: fp16 padded B images from W1 ----------------
// B[j][n][k] = W1_w[n][j*128 + k]
__global__ void prep_B(const float* __restrict__ W1) {
    int idx = blockIdx.x * blockDim.x + threadIdx.x;
    if (idx >= 3 * 128 * 64) return;
    int j = idx / 8192;
    int rem = idx - j * 8192;
    int row = rem >> 6;
    int kp = rem & 63;
    int k = kp << 1;
    float v0 = W1[row * 384 + j * 128 + k];
    float v1 = W1[row * 384 + j * 128 + k + 1];
    *(__half2*)&g_Bf[j][(uint32_t)row * AST + k] = __floats2half2_rn(v0, v1);
}

// ---------------- kernel 2: P = h @ W1^T, single-pass fp16 mma ----------------
#define SMEM_HALVES (128 * AST)
#define SMEM_TOTAL (2 * SMEM_HALVES * 2)   // 69632 bytes

__global__ void __launch_bounds__(256, 2) gemm_P(const float* __restrict__ hmat) {
    extern __shared__ __half sm[];
    __half* A = sm;
    __half* B = sm + SMEM_HALVES;

    int tid = threadIdx.x, w = tid >> 5, lane = tid & 31;
    int wm = w >> 2;      // 0..1  -> rows [wm*64, +64)
    int wn = w & 3;       // 0..3  -> cols [wn*32, +32)
    int base = blockIdx.x * 128;

    // Load + convert A tile [128 x 128] fp32 -> fp16 smem
    for (int p = tid; p < 128 * 64; p += 256) {
        int row = p >> 6, kp = p & 63;
        int node = base + row;
        float2 t = make_float2(0.f, 0.f);
        if (node < NNODES) t = *(const float2*)(hmat + (size_t)node * HF + (kp << 1));
        *(__half2*)&A[(uint32_t)row * AST + (kp << 1)] = __floats2half2_rn(t.x, t.y);
    }

    // ldmatrix lane mappings
    int a_row = wm * 64 + (lane & 15);
    int a_koff = (lane >> 4) << 3;
    int b_row = wn * 32 + (lane & 7) + ((lane >> 4) << 3);
    int b_koff = ((lane >> 3) & 1) << 3;

    for (int j = 0; j < 3; j++) {
        __syncthreads();
        // stage B_j into smem
        {
            const uint4* s = (const uint4*)g_Bf[j];
            uint4* d = (uint4*)B;
            #pragma unroll 3
            for (int i = tid; i < SMEM_HALVES / 8; i += 256) d[i] = s[i];
        }
        __syncthreads();

        float acc[4][4][4];
        #pragma unroll
        for (int mt = 0; mt < 4; mt++)
            #pragma unroll
            for (int nt = 0; nt < 4; nt++)
                #pragma unroll
                for (int q = 0; q < 4; q++) acc[mt][nt][q] = 0.f;

        #pragma unroll
        for (int ks = 0; ks < 8; ks++) {
            int kb = ks * 16;
            uint32_t af[4][4];
            #pragma unroll
            for (int mt = 0; mt < 4; mt++)
                ldsm4(af[mt], &A[(a_row + mt * 16) * AST + kb + a_koff]);
            #pragma unroll
            for (int bt = 0; bt < 2; bt++) {
                uint32_t bf[4];
                ldsm4(bf, &B[(b_row + bt * 16) * AST + kb + b_koff]);
                #pragma unroll
                for (int mt = 0; mt < 4; mt++) {
                    mma_f16(acc[mt][2 * bt], af[mt], bf[0], bf[1]);
                    mma_f16(acc[mt][2 * bt + 1], af[mt], bf[2], bf[3]);
                }
            }
        }

        // epilogue: store fp16 P
        __half* Pj = g_P + (size_t)j * NODES_PAD * HF;
        int r0 = base + wm * 64 + (lane >> 2);
        int c0 = wn * 32 + (lane & 3) * 2;
        #pragma unroll
        for (int mt = 0; mt < 4; mt++) {
            int ra = r0 + mt * 16, rb = ra + 8;
            #pragma unroll
            for (int nt = 0; nt < 4; nt++) {
                int col = c0 + nt * 8;
                if (ra < NNODES)
                    *(__half2*)(Pj + (size_t)ra * HF + col) =
                        __floats2half2_rn(acc[mt][nt][0], acc[mt][nt][1]);
                if (rb < NNODES)
                    *(__half2*)(Pj + (size_t)rb * HF + col) =
                        __floats2half2_rn(acc[mt][nt][2], acc[mt][nt][3]);
            }
        }
    }
}

// ---------------- kernel 3: gather + add + relu + layer-2 ----------------
// 16 lanes per triplet (2 triplets/warp), grid-stride, weights in registers.
__global__ void __launch_bounds__(256) mlp2_kernel(const void* __restrict__ trip,
                                                   const float* __restrict__ Wb1,
                                                   const float* __restrict__ W2,
                                                   const float* __restrict__ Wb2,
                                                   float* __restrict__ out, int T) {
    int sl = threadIdx.x & 15;             // lane within 16-group
    int sub = (threadIdx.x >> 4) & 1;      // which triplet of the warp
    int gw = (int)((blockIdx.x * blockDim.x + threadIdx.x) >> 5);
    int nw = (int)((gridDim.x * blockDim.x) >> 5);
    int is64 = g_is64;

    // hoisted weights: 8 cols per lane
    int c8 = sl << 3;
    float4 bA = *(const float4*)(Wb1 + c8);
    float4 bB = *(const float4*)(Wb1 + c8 + 4);
    float4 w0A = *(const float4*)(W2 + c8);
    float4 w0B = *(const float4*)(W2 + c8 + 4);
    float4 w1A = *(const float4*)(W2 + HF + c8);
    float4 w1B = *(const float4*)(W2 + HF + c8 + 4);
    float c0 = Wb2[0], c1 = Wb2[1];

    const __half* P0 = g_P;
    const __half* P1 = g_P + (size_t)NODES_PAD * HF;
    const __half* P2 = g_P + (size_t)2 * NODES_PAD * HF;

    for (int tt = gw * 2 + sub; tt < T; tt += 2 * nw) {
        long long t0, t1, t2;
        if (is64) {
            const long long* tp = (const long long*)trip + 3ll * tt;
            t0 = tp[0]; t1 = tp[1]; t2 = tp[2];
        } else {
            const int* tp = (const int*)trip + 3 * tt;
            t0 = tp[0]; t1 = tp[1]; t2 = tp[2];
        }

        uint4 ua = *(const uint4*)(P0 + (size_t)t0 * HF + c8);
        uint4 ub = *(const uint4*)(P1 + (size_t)t1 * HF + c8);
        uint4 uc = *(const uint4*)(P2 + (size_t)t2 * HF + c8);

        float2 a0 = __half22float2(*(const __half2*)&ua.x);
        float2 a1 = __half22float2(*(const __half2*)&ua.y);
        float2 a2 = __half22float2(*(const __half2*)&ua.z);
        float2 a3 = __half22float2(*(const __half2*)&ua.w);
        float2 b0 = __half22float2(*(const __half2*)&ub.x);
        float2 b1 = __half22float2(*(const __half2*)&ub.y);
        float2 b2 = __half22float2(*(const __half2*)&ub.z);
        float2 b3 = __half22float2(*(const __half2*)&ub.w);
        float2 d0 = __half22float2(*(const __half2*)&uc.x);
        float2 d1 = __half22float2(*(const __half2*)&uc.y);
        float2 d2 = __half22float2(*(const __half2*)&uc.z);
        float2 d3 = __half22float2(*(const __half2*)&uc.w);

        float h0 = fmaxf(a0.x + b0.x + d0.x + bA.x, 0.f);
        float h1 = fmaxf(a0.y + b0.y + d0.y + bA.y, 0.f);
        float h2 = fmaxf(a1.x + b1.x + d1.x + bA.z, 0.f);
        float h3 = fmaxf(a1.y + b1.y + d1.y + bA.w, 0.f);
        float h4 = fmaxf(a2.x + b2.x + d2.x + bB.x, 0.f);
        float h5 = fmaxf(a2.y + b2.y + d2.y + bB.y, 0.f);
        float h6 = fmaxf(a3.x + b3.x + d3.x + bB.z, 0.f);
        float h7 = fmaxf(a3.y + b3.y + d3.y + bB.w, 0.f);

        float acc0 = h0 * w0A.x + h1 * w0A.y + h2 * w0A.z + h3 * w0A.w
                   + h4 * w0B.x + h5 * w0B.y + h6 * w0B.z + h7 * w0B.w;
        float acc1 = h0 * w1A.x + h1 * w1A.y + h2 * w1A.z + h3 * w1A.w
                   + h4 * w1B.x + h5 * w1B.y + h6 * w1B.z + h7 * w1B.w;

        #pragma unroll
        for (int m = 8; m; m >>= 1) {
            acc0 += __shfl_xor_sync(0xffffffffu, acc0, m);
            acc1 += __shfl_xor_sync(0xffffffffu, acc1, m);
        }
        if (sl == 0) {
            float2 o;
            o.x = acc0 + c0;
            o.y = acc1 + c1;
            *(float2*)(out + 2ll * tt) = o;
        }
    }
}

// ---------------- launch ----------------
extern "C" void kernel_launch(void* const* d_in, const int* in_sizes, int n_in,
                              void* d_out, int out_size) {
    const float* hmat = (const float*)d_in[0];
    const void* trip = d_in[1];
    const float* W1w = (const float*)d_in[2];
    const float* W1b = (const float*)d_in[3];
    const float* W2w = (const float*)d_in[4];
    const float* W2b = (const float*)d_in[5];
    float* out = (float*)d_out;
    int T = in_sizes[1] / 3;

    static int smem_set = 0;
    if (!smem_set) {
        cudaFuncSetAttribute(gemm_P, cudaFuncAttributeMaxDynamicSharedMemorySize, SMEM_TOTAL);
        smem_set = 1;
    }

    detect_kernel<<<1, 256>>>((const unsigned*)trip, in_sizes[1]);
    prep_B<<<(3 * 128 * 64 + 255) / 256, 256>>>(W1w);
    gemm_P<<<MTILES, 256, SMEM_TOTAL>>>(hmat);
    mlp2_kernel<<<1480, 256>>>(trip, W1b, W2w, W2b, out, T);
}

// round 5
// speedup vs baseline: 1.9430x; 1.1986x over previous
#include <cuda_runtime.h>
#include <cuda_bf16.h>
#include <cuda_fp16.h>
#include <cstdint>

#define HF 128
#define NNODES 100000
#define NODES_PAD 100096
#define MTILES 782   // ceil(100000/128)
#define AST 136      // padded row stride in halves (272B)

// ---------------- device scratch ----------------
__device__ __half g_P[(size_t)3 * NODES_PAD * HF];   // 76.9 MB fp16 P tables
__device__ __half g_Bf[3][128 * AST];                // fp16 padded B images
__device__ int g_is64;

// ---------------- helpers ----------------
static __device__ __forceinline__ void ldsm4(uint32_t* r, const void* p) {
    uint32_t a = (uint32_t)__cvta_generic_to_shared(p);
    asm volatile("ldmatrix.sync.aligned.m8n8.x4.shared.b16 {%0,%1,%2,%3}, [%4];"
                 : "=r"(r[0]), "=r"(r[1]), "=r"(r[2]), "=r"(r[3]) : "r"(a));
}
static __device__ __forceinline__ void mma_f16(float* c, const uint32_t* a,
                                               uint32_t b0, uint32_t b1) {
    asm volatile(
        "mma.sync.aligned.m16n8k16.row.col.f32.f16.f16.f32 "
        "{%0,%1,%2,%3}, {%4,%5,%6,%7}, {%8,%9}, {%0,%1,%2,%3};"
        : "+f"(c[0]), "+f"(c[1]), "+f"(c[2]), "+f"(c[3])
        : "r"(a[0]), "r"(a[1]), "r"(a[2]), "r"(a[3]), "r"(b0), "r"(b1));
}
static __device__ __forceinline__ void cpa16(void* s, const void* g) {
    uint32_t sa = (uint32_t)__cvta_generic_to_shared(s);
    asm volatile("cp.async.ca.shared.global [%0], [%1], 16;" :: "r"(sa), "l"(g));
}
#define CP_COMMIT() asm volatile("cp.async.commit_group;" ::: "memory")
#define CP_WAIT0()  asm volatile("cp.async.wait_group 0;" ::: "memory")

// ---------------- kernel 0: detect triplet dtype ----------------
__global__ void detect_kernel(const unsigned* __restrict__ w, int total_words) {
    __shared__ int zc, ts;
    if (threadIdx.x == 0) { zc = 0; ts = 0; }
    __syncthreads();
    int maxi = (total_words - 1) >> 1;
    int samples = maxi < 4096 ? maxi : 4096;
    int stride = samples > 0 ? (maxi / samples) : 1;
    if (stride < 1) stride = 1;
    int lz = 0, lt = 0;
    for (int s = threadIdx.x; s < samples; s += blockDim.x) {
        int i = s * stride;
        lt++;
        if (w[2 * i + 1] == 0u) lz++;
    }
    atomicAdd(&zc, lz);
    atomicAdd(&ts, lt);
    __syncthreads();
    if (threadIdx.x == 0) g_is64 = (2 * zc > ts) ? 1 : 0;
}

// ---------------- kernel 1: fp16 padded B images from W1 ----------------
__global__ void prep_B(const float* __restrict__ W1) {
    int idx = blockIdx.x * blockDim.x + threadIdx.x;
    if (idx >= 3 * 128 * 64) return;
    int j = idx / 8192;
    int rem = idx - j * 8192;
    int row = rem >> 6;
    int kp = rem & 63;
    int k = kp << 1;
    float v0 = W1[row * 384 + j * 128 + k];
    float v1 = W1[row * 384 + j * 128 + k + 1];
    *(__half2*)&g_Bf[j][(uint32_t)row * AST + k] = __floats2half2_rn(v0, v1);
}

// ---------------- kernel 2: P = h @ W1^T, fp16 mma, cp.async dbl-buffered B ----------------
#define SMEM_HALVES (128 * AST)
#define BBYTES (SMEM_HALVES * 2)            // 34816
#define SMEM_TOTAL (3 * BBYTES)             // 104448 bytes: A + B0 + B1

__global__ void __launch_bounds__(256, 2) gemm_P(const float* __restrict__ hmat) {
    extern __shared__ __half sm[];
    __half* A = sm;
    __half* Bbuf[2] = { sm + SMEM_HALVES, sm + 2 * SMEM_HALVES };

    int tid = threadIdx.x, w = tid >> 5, lane = tid & 31;
    int wm = w >> 2;
    int wn = w & 3;
    int base = blockIdx.x * 128;

    // prefetch B0 via cp.async (overlaps with the A load below)
    {
        const char* src = (const char*)g_Bf[0];
        char* dst = (char*)Bbuf[0];
        for (int i = tid; i < BBYTES / 16; i += 256) cpa16(dst + i * 16, src + i * 16);
        CP_COMMIT();
    }

    // Load + convert A tile [128 x 128] fp32 -> fp16 smem
    for (int p = tid; p < 128 * 64; p += 256) {
        int row = p >> 6, kp = p & 63;
        int node = base + row;
        float2 t = make_float2(0.f, 0.f);
        if (node < NNODES) t = *(const float2*)(hmat + (size_t)node * HF + (kp << 1));
        *(__half2*)&A[(uint32_t)row * AST + (kp << 1)] = __floats2half2_rn(t.x, t.y);
    }
    CP_WAIT0();
    __syncthreads();

    int a_row = wm * 64 + (lane & 15);
    int a_koff = (lane >> 4) << 3;
    int b_row = wn * 32 + (lane & 7) + ((lane >> 4) << 3);
    int b_koff = ((lane >> 3) & 1) << 3;

    for (int j = 0; j < 3; j++) {
        __half* B = Bbuf[j & 1];
        // prefetch next B into the other buffer (safe: all warps finished reading it
        // before the barrier that started this iteration)
        if (j < 2) {
            const char* src = (const char*)g_Bf[j + 1];
            char* dst = (char*)Bbuf[(j + 1) & 1];
            for (int i = tid; i < BBYTES / 16; i += 256) cpa16(dst + i * 16, src + i * 16);
            CP_COMMIT();
        }

        float acc[4][4][4];
        #pragma unroll
        for (int mt = 0; mt < 4; mt++)
            #pragma unroll
            for (int nt = 0; nt < 4; nt++)
                #pragma unroll
                for (int q = 0; q < 4; q++) acc[mt][nt][q] = 0.f;

        #pragma unroll
        for (int ks = 0; ks < 8; ks++) {
            int kb = ks * 16;
            uint32_t af[4][4], bf[2][4];
            #pragma unroll
            for (int mt = 0; mt < 4; mt++)
                ldsm4(af[mt], &A[(a_row + mt * 16) * AST + kb + a_koff]);
            #pragma unroll
            for (int bt = 0; bt < 2; bt++)
                ldsm4(bf[bt], &B[(b_row + bt * 16) * AST + kb + b_koff]);
            #pragma unroll
            for (int bt = 0; bt < 2; bt++)
                #pragma unroll
                for (int mt = 0; mt < 4; mt++) {
                    mma_f16(acc[mt][2 * bt], af[mt], bf[bt][0], bf[bt][1]);
                    mma_f16(acc[mt][2 * bt + 1], af[mt], bf[bt][2], bf[bt][3]);
                }
        }

        // epilogue: store fp16 P
        __half* Pj = g_P + (size_t)j * NODES_PAD * HF;
        int r0 = base + wm * 64 + (lane >> 2);
        int c0 = wn * 32 + (lane & 3) * 2;
        #pragma unroll
        for (int mt = 0; mt < 4; mt++) {
            int ra = r0 + mt * 16, rb = ra + 8;
            #pragma unroll
            for (int nt = 0; nt < 4; nt++) {
                int col = c0 + nt * 8;
                if (ra < NNODES)
                    *(__half2*)(Pj + (size_t)ra * HF + col) =
                        __floats2half2_rn(acc[mt][nt][0], acc[mt][nt][1]);
                if (rb < NNODES)
                    *(__half2*)(Pj + (size_t)rb * HF + col) =
                        __floats2half2_rn(acc[mt][nt][2], acc[mt][nt][3]);
            }
        }

        if (j < 2) CP_WAIT0();
        __syncthreads();
    }
}

// ---------------- kernel 3: gather + add + relu + layer-2 ----------------
// 16 lanes per triplet, TWO triplets in flight per group, persistent grid.
__global__ void __launch_bounds__(256, 4) mlp2_kernel(const void* __restrict__ trip,
                                                      const float* __restrict__ Wb1,
                                                      const float* __restrict__ W2,
                                                      const float* __restrict__ Wb2,
                                                      float* __restrict__ out, int T) {
    int tid = threadIdx.x;
    int sl = tid & 15;
    int grp = (int)((blockIdx.x * blockDim.x + tid) >> 4);
    int ngrp = (int)((gridDim.x * blockDim.x) >> 4);
    int is64 = g_is64;
    int sw = is64 ? 6 : 3, ew = is64 ? 2 : 1;
    int c8 = sl << 3;

    // weights hoisted as fp16 (12 regs)
    __half2 wb[4], w0h[4], w1h[4];
    {
        float4 a = *(const float4*)(Wb1 + c8), b = *(const float4*)(Wb1 + c8 + 4);
        wb[0] = __floats2half2_rn(a.x, a.y); wb[1] = __floats2half2_rn(a.z, a.w);
        wb[2] = __floats2half2_rn(b.x, b.y); wb[3] = __floats2half2_rn(b.z, b.w);
        a = *(const float4*)(W2 + c8); b = *(const float4*)(W2 + c8 + 4);
        w0h[0] = __floats2half2_rn(a.x, a.y); w0h[1] = __floats2half2_rn(a.z, a.w);
        w0h[2] = __floats2half2_rn(b.x, b.y); w0h[3] = __floats2half2_rn(b.z, b.w);
        a = *(const float4*)(W2 + HF + c8); b = *(const float4*)(W2 + HF + c8 + 4);
        w1h[0] = __floats2half2_rn(a.x, a.y); w1h[1] = __floats2half2_rn(a.z, a.w);
        w1h[2] = __floats2half2_rn(b.x, b.y); w1h[3] = __floats2half2_rn(b.z, b.w);
    }
    float c0 = Wb2[0], c1 = Wb2[1];

    const char* P0 = (const char*)g_P;
    const char* P1 = P0 + (size_t)NODES_PAD * HF * 2;
    const char* P2 = P1 + (size_t)NODES_PAD * HF * 2;
    const unsigned* tw = (const unsigned*)trip;
    uint32_t cb = (uint32_t)(c8 << 1);  // byte offset within row

    for (int t = grp * 2; t < T; t += ngrp * 2) {
        int bw = t * sw;
        unsigned i00 = tw[bw], i01 = tw[bw + ew], i02 = tw[bw + 2 * ew];
        bool two = (t + 1) < T;
        unsigned i10 = i00, i11 = i01, i12 = i02;
        if (two) { i10 = tw[bw + sw]; i11 = tw[bw + sw + ew]; i12 = tw[bw + sw + 2 * ew]; }

        // 6 gathers issued together (MLP=6)
        uint4 ua0 = *(const uint4*)(P0 + ((size_t)i00 << 8) + cb);
        uint4 ub0 = *(const uint4*)(P1 + ((size_t)i01 << 8) + cb);
        uint4 uc0 = *(const uint4*)(P2 + ((size_t)i02 << 8) + cb);
        uint4 ua1 = *(const uint4*)(P0 + ((size_t)i10 << 8) + cb);
        uint4 ub1 = *(const uint4*)(P1 + ((size_t)i11 << 8) + cb);
        uint4 uc1 = *(const uint4*)(P2 + ((size_t)i12 << 8) + cb);

        float acc00 = 0.f, acc01 = 0.f, acc10 = 0.f, acc11 = 0.f;
        #pragma unroll
        for (int q = 0; q < 4; q++) {
            float2 bias = __half22float2(wb[q]);
            float2 w0 = __half22float2(w0h[q]);
            float2 w1 = __half22float2(w1h[q]);
            // triplet 0
            {
                float2 fa = __half22float2(((const __half2*)&ua0)[q]);
                float2 fb = __half22float2(((const __half2*)&ub0)[q]);
                float2 fc = __half22float2(((const __half2*)&uc0)[q]);
                float hx = fmaxf(fa.x + fb.x + fc.x + bias.x, 0.f);
                float hy = fmaxf(fa.y + fb.y + fc.y + bias.y, 0.f);
                acc00 += hx * w0.x + hy * w0.y;
                acc01 += hx * w1.x + hy * w1.y;
            }
            // triplet 1
            {
                float2 fa = __half22float2(((const __half2*)&ua1)[q]);
                float2 fb = __half22float2(((const __half2*)&ub1)[q]);
                float2 fc = __half22float2(((const __half2*)&uc1)[q]);
                float hx = fmaxf(fa.x + fb.x + fc.x + bias.x, 0.f);
                float hy = fmaxf(fa.y + fb.y + fc.y + bias.y, 0.f);
                acc10 += hx * w0.x + hy * w0.y;
                acc11 += hx * w1.x + hy * w1.y;
            }
        }

        #pragma unroll
        for (int m = 8; m; m >>= 1) {
            acc00 += __shfl_xor_sync(0xffffffffu, acc00, m);
            acc01 += __shfl_xor_sync(0xffffffffu, acc01, m);
            acc10 += __shfl_xor_sync(0xffffffffu, acc10, m);
            acc11 += __shfl_xor_sync(0xffffffffu, acc11, m);
        }
        if (sl == 0) {
            if (two) {
                float4 o;
                o.x = acc00 + c0; o.y = acc01 + c1;
                o.z = acc10 + c0; o.w = acc11 + c1;
                *(float4*)(out + 2ll * t) = o;
            } else {
                float2 o;
                o.x = acc00 + c0; o.y = acc01 + c1;
                *(float2*)(out + 2ll * t) = o;
            }
        }
    }
}

// ---------------- launch ----------------
extern "C" void kernel_launch(void* const* d_in, const int* in_sizes, int n_in,
                              void* d_out, int out_size) {
    const float* hmat = (const float*)d_in[0];
    const void* trip = d_in[1];
    const float* W1w = (const float*)d_in[2];
    const float* W1b = (const float*)d_in[3];
    const float* W2w = (const float*)d_in[4];
    const float* W2b = (const float*)d_in[5];
    float* out = (float*)d_out;
    int T = in_sizes[1] / 3;

    static int smem_set = 0;
    if (!smem_set) {
        cudaFuncSetAttribute(gemm_P, cudaFuncAttributeMaxDynamicSharedMemorySize, SMEM_TOTAL);
        smem_set = 1;
    }

    detect_kernel<<<1, 256>>>((const unsigned*)trip, in_sizes[1]);
    prep_B<<<(3 * 128 * 64 + 255) / 256, 256>>>(W1w);
    gemm_P<<<MTILES, 256, SMEM_TOTAL>>>(hmat);
    mlp2_kernel<<<592, 256>>>(trip, W1b, W2w, W2b, out, T);
}